// round 13
// baseline (speedup 1.0000x reference)
#include <cuda_runtime.h>
#include <math.h>
#include <stdint.h>

// EdgeEmbedding: pure elementwise map over edges (R0 analysis: the pair
// segment-mean and SH parity cancel bit-exactly):
//   edge_length    = ||edge_vec||
//   edge_embedding = bessel(||edge_vec||) * cutoff(||edge_vec||)
//   edge_attr      = SH_l<=2(edge_vec / ||edge_vec||)
// Output layout: [len (E) | emb (E,8) | attr (E,9)].
//
// R8 = R7 (warp-private staging, no block sync, coalesced float4 input,
// streaming hints) + 2 edge-groups per warp: both input LDG.128 batches
// issue back-to-back before compute (2x per-warp MLP), one __syncwarp,
// half the grid. Compute for the two groups is sequenced to keep register
// pressure ~40 so occupancy stays ~48 warps/SM.

#define EPB 512   // edges per block (256 threads, 2 edges/thread)

__device__ __forceinline__ void edge_math(float x, float y, float z,
                                          float& len, float* emb8, float* attr9)
{
    const float S3   = 1.7320508075688772f;   // sqrt(3)
    const float S5   = 2.2360679774997896f;   // sqrt(5)
    const float S15  = 3.8729833462074170f;   // sqrt(15)
    const float PI_F = 3.14159265358979323846f;
    const float SQRT_2_OVER_RC = 0.6324555320336759f; // sqrt(2/5)
    const float INV_RC = 0.2f;

    float r2  = fmaf(x, x, fmaf(y, y, z * z));
    float inv = rsqrtf(fmaxf(r2, 1e-24f));    // 1/r  (single MUFU.RSQ)
    float r   = r2 * inv;                     // r = r2 / sqrt(r2)
    len = r;

    // spherical harmonics l<=2 on u = vec/r
    float ux = x * inv, uy = y * inv, uz = z * inv;
    attr9[0] = 1.0f;
    attr9[1] = S3 * ux;
    attr9[2] = S3 * uy;
    attr9[3] = S3 * uz;
    attr9[4] = S15 * ux * uy;
    attr9[5] = S15 * uy * uz;
    attr9[6] = 0.5f * S5 * fmaf(3.0f * uz, uz, -1.0f);
    attr9[7] = S15 * ux * uz;
    attr9[8] = 0.5f * S15 * (ux * ux - uy * uy);

    // polynomial cutoff (p=6): 1 - 28 q^6 + 48 q^7 - 21 q^8
    float q  = r * INV_RC;
    float q2 = q * q;
    float q3 = q2 * q;
    float q6 = q3 * q3;
    float env = fmaf(q6, fmaf(q, fmaf(-21.0f, q, 48.0f), -28.0f), 1.0f);
    env = (q < 1.0f) ? env : 0.0f;

    // bessel: sqrt(2/RC) * sin(k*pi*q)/r_safe * env, k=1..8
    // Chebyshev recurrence: sin((k+1)t) = 2cos(t)sin(kt) - sin((k-1)t)
    float st, ct;
    __sincosf(PI_F * q, &st, &ct);            // MUFU sin/cos, |x| <= ~pi
    float pre  = SQRT_2_OVER_RC * inv * env;
    float twoc = 2.0f * ct;
    float sk_m1 = 0.0f, sk = st;
#pragma unroll
    for (int k = 0; k < 8; k++) {
        emb8[k] = pre * sk;
        float nxt = fmaf(twoc, sk, -sk_m1);
        sk_m1 = sk;
        sk = nxt;
    }
}

__device__ __forceinline__ void emit_edge(float* __restrict__ out, long long E,
                                          long long e, int vec_ok,
                                          float x, float y, float z,
                                          float* __restrict__ stage /*or null*/,
                                          int lane)
{
    float len, emb[8], a9[9];
    edge_math(x, y, z, len, emb, a9);

    // len: naturally coalesced
    __stcs(&out[e], len);

    // emb: direct from registers (each float4 is one thread's data)
    float* oe = out + E + e * 8;
    if (vec_ok) {
        float4* pe = reinterpret_cast<float4*>(oe);
        __stcs(&pe[0], make_float4(emb[0], emb[1], emb[2], emb[3]));
        __stcs(&pe[1], make_float4(emb[4], emb[5], emb[6], emb[7]));
    } else {
#pragma unroll
        for (int k = 0; k < 8; k++) oe[k] = emb[k];
    }

    if (stage) {
        // stride-9 STS (9 perp 32 -> bank-conflict-free)
#pragma unroll
        for (int k = 0; k < 9; k++) stage[lane * 9 + k] = a9[k];
    } else {
        float* oa = out + 9 * E + e * 9;
#pragma unroll
        for (int k = 0; k < 9; k++) oa[k] = a9[k];
    }
}

__global__ __launch_bounds__(256)
void edge_embed_r8(const float* __restrict__ vec,
                   float* __restrict__ out,
                   int E, int vec_ok)
{
    // per-warp slices: 192 input floats, 576 attr floats (2 groups)
    __shared__ float in_s[8][192];
    __shared__ float attr_s[8][576];

    const int tid  = threadIdx.x;
    const int lane = tid & 31;
    const int wid  = tid >> 5;
    const long long base = (long long)blockIdx.x * EPB;
    const long long g0 = base + wid * 64;     // warp's first edge
    const long long e0 = g0 + lane;
    const long long e1 = e0 + 32;

    const bool v0 = e0 < (long long)E;
    const bool v1 = e1 < (long long)E;
    const bool full_both = ((g0 + 64) <= (long long)E) && vec_ok;
    const bool full0     = ((g0 + 32) <= (long long)E) && vec_ok;

    float x0 = 0.f, y0 = 0.f, z0 = 0.f, x1 = 0.f, y1 = 0.f, z1 = 0.f;

    if (full_both) {
        // both groups: 48 coalesced LDG.128, all in flight before compute
        const float4* v4 = reinterpret_cast<const float4*>(vec + g0 * 3);
        float4* s4 = reinterpret_cast<float4*>(in_s[wid]);
        if (lane < 24) {
            float4 a = __ldcs(&v4[lane]);
            float4 b = __ldcs(&v4[lane + 24]);
            s4[lane]      = a;
            s4[lane + 24] = b;
        }
        __syncwarp();
        x0 = in_s[wid][3 * lane + 0];
        y0 = in_s[wid][3 * lane + 1];
        z0 = in_s[wid][3 * lane + 2];
        x1 = in_s[wid][96 + 3 * lane + 0];
        y1 = in_s[wid][96 + 3 * lane + 1];
        z1 = in_s[wid][96 + 3 * lane + 2];
    } else {
        if (v0) { x0 = vec[3*e0]; y0 = vec[3*e0+1]; z0 = vec[3*e0+2]; }
        if (v1) { x1 = vec[3*e1]; y1 = vec[3*e1+1]; z1 = vec[3*e1+2]; }
    }

    // sequenced compute keeps register pressure low; stores are
    // fire-and-forget so the two groups still overlap in the memory system
    if (v0)
        emit_edge(out, E, e0, vec_ok, x0, y0, z0,
                  full0 ? attr_s[wid] : nullptr, lane);
    if (v1)
        emit_edge(out, E, e1, vec_ok, x1, y1, z1,
                  full_both ? attr_s[wid] + 288 : nullptr, lane);

    // attr writeout: contiguous float4 region per warp; bases 16B-aligned
    // (9E with E%4==0, g0*9 = (512*bid + 64*wid)*9 both multiples of 4)
    if (full_both) {
        __syncwarp();
        const float4* s4 = reinterpret_cast<const float4*>(attr_s[wid]);
        float4* g4 = reinterpret_cast<float4*>(out + 9LL * E + g0 * 9);
        __stcs(&g4[lane],       s4[lane]);
        __stcs(&g4[lane + 32],  s4[lane + 32]);
        __stcs(&g4[lane + 64],  s4[lane + 64]);
        __stcs(&g4[lane + 96],  s4[lane + 96]);
        if (lane < 16)
            __stcs(&g4[lane + 128], s4[lane + 128]);
    } else if (full0) {
        __syncwarp();
        const float4* s4 = reinterpret_cast<const float4*>(attr_s[wid]);
        float4* g4 = reinterpret_cast<float4*>(out + 9LL * E + g0 * 9);
        __stcs(&g4[lane],      s4[lane]);
        __stcs(&g4[lane + 32], s4[lane + 32]);
        if (lane < 8)
            __stcs(&g4[lane + 64], s4[lane + 64]);
    }
}

extern "C" void kernel_launch(void* const* d_in, const int* in_sizes, int n_in,
                              void* d_out, int out_size)
{
    const float* edge_vec = (const float*)d_in[0];
    int E = in_sizes[0] / 3;
    float* out = (float*)d_out;

    // vectorized paths require 16B alignment of out+E (offset 8e), the attr
    // warp bases (9E + 9*g0), and input warp bases (12B*64-edge groups)
    // -> E % 4 == 0.
    int vec_ok = ((E & 3) == 0) ? 1 : 0;

    int blocks = (E + EPB - 1) / EPB;
    edge_embed_r8<<<blocks, 256>>>(edge_vec, out, E, vec_ok);
}